// round 6
// baseline (speedup 1.0000x reference)
#include <cuda_runtime.h>
#include <cuda_bf16.h>
#include <math.h>
#include <stdint.h>

// Problem constants
#define BB 2
#define SS 1024
#define DD 512
#define VV 32000
#define MM 2048
#define G3 1536
#define GRU_CTAS 128

// ---------------- scratch ----------------
__device__ float d_xproj[MM * G3];
__device__ float d_gru[MM * DD];
__device__ float d_h[2][BB * DD];
__device__ unsigned d_bar;
__device__ float d_Q[MM * DD];
__device__ float d_Kc[MM * DD];
__device__ float d_probs[BB * SS * SS];
__device__ float d_ctx[MM * DD];
__device__ uint8_t d_comb_f8[MM * 2 * DD];            // e4m3, x16 scale
__device__ uint8_t d_genW_f8[(size_t)VV * 2 * DD];    // e4m3, x64 scale
__device__ float d_gate[MM];
__device__ float d_logits[65536000];

// =====================================================================
// K1: x_emb gather + x_proj
// =====================================================================
__global__ void k_xproj(const int* __restrict__ x,
                        const float* __restrict__ tok_emb,
                        const float* __restrict__ pos_emb,
                        const float* __restrict__ W_ih,
                        const float* __restrict__ b_ih)
{
    const int m0 = blockIdx.y * 64;
    const int n0 = blockIdx.x * 64;
    __shared__ float As[16][64];
    __shared__ float Bs[16][64];
    __shared__ int tokS[64];
    __shared__ int sS[64];

    const int t = threadIdx.x;
    if (t < 64) {
        int m = m0 + t;
        int b = m & 1, s = m >> 1;
        tokS[t] = x[b * SS + s];
        sS[t] = s;
    }
    __syncthreads();

    const int lrow = t >> 2;
    const int lk4  = (t & 3) * 4;
    const int ty = t >> 4, tx = t & 15;
    float acc[4][4];
#pragma unroll
    for (int i = 0; i < 4; i++)
#pragma unroll
        for (int j = 0; j < 4; j++) acc[i][j] = 0.f;

    for (int k0 = 0; k0 < DD; k0 += 16) {
        float4 te = *(const float4*)&tok_emb[(size_t)tokS[lrow] * DD + k0 + lk4];
        float4 pe = *(const float4*)&pos_emb[(size_t)sS[lrow] * DD + k0 + lk4];
        float4 bv = *(const float4*)&W_ih[(size_t)(n0 + lrow) * DD + k0 + lk4];
        As[lk4 + 0][lrow] = te.x + pe.x;
        As[lk4 + 1][lrow] = te.y + pe.y;
        As[lk4 + 2][lrow] = te.z + pe.z;
        As[lk4 + 3][lrow] = te.w + pe.w;
        Bs[lk4 + 0][lrow] = bv.x;
        Bs[lk4 + 1][lrow] = bv.y;
        Bs[lk4 + 2][lrow] = bv.z;
        Bs[lk4 + 3][lrow] = bv.w;
        __syncthreads();
#pragma unroll
        for (int kk = 0; kk < 16; kk++) {
            float4 av = *(float4*)&As[kk][ty * 4];
            float4 bv2 = *(float4*)&Bs[kk][tx * 4];
            float a[4] = {av.x, av.y, av.z, av.w};
            float b2[4] = {bv2.x, bv2.y, bv2.z, bv2.w};
#pragma unroll
            for (int i = 0; i < 4; i++)
#pragma unroll
                for (int j = 0; j < 4; j++) acc[i][j] += a[i] * b2[j];
        }
        __syncthreads();
    }
#pragma unroll
    for (int i = 0; i < 4; i++) {
        int m = m0 + ty * 4 + i;
#pragma unroll
        for (int j = 0; j < 4; j++) {
            int n = n0 + tx * 4 + j;
            d_xproj[(size_t)m * G3 + n] = acc[i][j] + b_ih[n];
        }
    }
}

// =====================================================================
// K2: init barrier + h0
// =====================================================================
__global__ void k_init()
{
    int t = threadIdx.x;
    for (int i = t; i < 2 * BB * DD; i += blockDim.x) ((float*)d_h)[i] = 0.f;
    if (t == 0) d_bar = 0u;
}

// =====================================================================
// K2b: convert gen_W to e4m3 (x64 scale)
// =====================================================================
__device__ __forceinline__ uint16_t cvt_e4m3x2(float hi, float lo)
{
    uint16_t p;
    asm("cvt.rn.satfinite.e4m3x2.f32 %0, %1, %2;" : "=h"(p) : "f"(hi), "f"(lo));
    return p;
}

__global__ void k_convW8(const float* __restrict__ W)
{
    size_t i = ((size_t)blockIdx.x * 256 + threadIdx.x) * 8;
    float4 f0 = *(const float4*)&W[i];
    float4 f1 = *(const float4*)&W[i + 4];
    uint16_t p[4];
    p[0] = cvt_e4m3x2(f0.y * 64.f, f0.x * 64.f);
    p[1] = cvt_e4m3x2(f0.w * 64.f, f0.z * 64.f);
    p[2] = cvt_e4m3x2(f1.y * 64.f, f1.x * 64.f);
    p[3] = cvt_e4m3x2(f1.w * 64.f, f1.z * 64.f);
    *(uint2*)&d_genW_f8[i] = *(uint2*)p;
}

// =====================================================================
// K3: GRU recurrence (persistent; xproj loads hoisted above poll)
// =====================================================================
__global__ void k_gru(const float* __restrict__ W_hh,
                      const float* __restrict__ b_hh)
{
    __shared__ float Wsm[4 * 3 * DD];
    __shared__ float h_sm[BB * DD];

    const int t = threadIdx.x;
    const int c = blockIdx.x;
    const int d_base = c * 4;

    for (int i = t; i < 1536; i += 256) {
        int fi = i * 4;
        int dl = fi / 1536;
        int rem = fi - dl * 1536;
        int g = rem / 512;
        int k = rem & 511;
        *(float4*)&Wsm[fi] =
            *(const float4*)&W_hh[(size_t)(g * DD + d_base + dl) * DD + k];
    }

    const int w = t >> 5, lane = t & 31;
    const int b = w & 1, dl = w >> 1;
    const int d = d_base + dl;
    const float bh_r = b_hh[d];
    const float bh_z = b_hh[DD + d];
    const float bh_n = b_hh[2 * DD + d];
    const float* Wr = &Wsm[(dl * 3 + 0) * DD];
    const float* Wz = &Wsm[(dl * 3 + 1) * DD];
    const float* Wn = &Wsm[(dl * 3 + 2) * DD];
    __syncthreads();

    unsigned long long bar_addr;
    asm("cvta.global.u64 %0, %1;" : "=l"(bar_addr) : "l"(&d_bar));

    for (int s = 0; s < SS; ++s) {
        // xproj loads are independent of h: issue BEFORE the barrier poll
        float xr = 0.f, xz = 0.f, xn = 0.f;
        if (lane == 0) {
            const float* xp = &d_xproj[(size_t)(s * 2 + b) * G3];
            xr = xp[d]; xz = xp[DD + d]; xn = xp[2 * DD + d];
        }

        if (s > 0 && t == 0) {
            unsigned target = (unsigned)GRU_CTAS * (unsigned)s;
            unsigned v;
            do {
                asm volatile("ld.acquire.gpu.global.u32 %0, [%1];"
                             : "=r"(v) : "l"(bar_addr));
            } while (v < target);
        }
        __syncthreads();

        float4 hv = __ldcv((const float4*)&d_h[s & 1][0] + t);
        *(float4*)&h_sm[t * 4] = hv;
        __syncthreads();

        const float* hb = &h_sm[b * DD];
        float a0 = 0.f, a1 = 0.f, a2 = 0.f;
#pragma unroll
        for (int k = 0; k < 16; k++) {
            float hv2 = hb[lane * 16 + k];
            a0 = fmaf(hv2, Wr[lane * 16 + k], a0);
            a1 = fmaf(hv2, Wz[lane * 16 + k], a1);
            a2 = fmaf(hv2, Wn[lane * 16 + k], a2);
        }
#pragma unroll
        for (int off = 16; off > 0; off >>= 1) {
            a0 += __shfl_down_sync(0xffffffffu, a0, off);
            a1 += __shfl_down_sync(0xffffffffu, a1, off);
            a2 += __shfl_down_sync(0xffffffffu, a2, off);
        }
        if (lane == 0) {
            float r = 1.f / (1.f + expf(-(xr + a0 + bh_r)));
            float z = 1.f / (1.f + expf(-(xz + a1 + bh_z)));
            float n = tanhf(xn + r * (a2 + bh_n));
            float hold = hb[d];
            float hn = (1.f - z) * n + z * hold;
            d_h[(s + 1) & 1][b * DD + d] = hn;
            d_gru[(size_t)(b * SS + s) * DD + d] = hn;
        }
        __syncthreads();
        if (t == 0)
            asm volatile("red.release.gpu.global.add.u32 [%0], %1;"
                         :: "l"(bar_addr), "r"(1u) : "memory");
    }
}

// =====================================================================
// K4: Q/K projection
// =====================================================================
template <int SEL>
__global__ void k_qk(const float* __restrict__ W)
{
    const int m0 = blockIdx.y * 64;
    const int n0 = blockIdx.x * 64;
    __shared__ float As[16][64];
    __shared__ float Bs[16][64];
    const int t = threadIdx.x;
    const int lrow = t >> 2, lk4 = (t & 3) * 4;
    const int ty = t >> 4, tx = t & 15;
    float acc[4][4];
#pragma unroll
    for (int i = 0; i < 4; i++)
#pragma unroll
        for (int j = 0; j < 4; j++) acc[i][j] = 0.f;

    for (int k0 = 0; k0 < DD; k0 += 16) {
        float4 a = *(const float4*)&d_gru[(size_t)(m0 + lrow) * DD + k0 + lk4];
        float4 bv = *(const float4*)&W[(size_t)(n0 + lrow) * DD + k0 + lk4];
        As[lk4 + 0][lrow] = a.x; As[lk4 + 1][lrow] = a.y;
        As[lk4 + 2][lrow] = a.z; As[lk4 + 3][lrow] = a.w;
        Bs[lk4 + 0][lrow] = bv.x; Bs[lk4 + 1][lrow] = bv.y;
        Bs[lk4 + 2][lrow] = bv.z; Bs[lk4 + 3][lrow] = bv.w;
        __syncthreads();
#pragma unroll
        for (int kk = 0; kk < 16; kk++) {
            float4 av = *(float4*)&As[kk][ty * 4];
            float4 bv2 = *(float4*)&Bs[kk][tx * 4];
            float a2[4] = {av.x, av.y, av.z, av.w};
            float b2[4] = {bv2.x, bv2.y, bv2.z, bv2.w};
#pragma unroll
            for (int i = 0; i < 4; i++)
#pragma unroll
                for (int j = 0; j < 4; j++) acc[i][j] += a2[i] * b2[j];
        }
        __syncthreads();
    }
    float* C = SEL ? d_Kc : d_Q;
#pragma unroll
    for (int i = 0; i < 4; i++)
#pragma unroll
        for (int j = 0; j < 4; j++)
            C[(size_t)(m0 + ty * 4 + i) * DD + n0 + tx * 4 + j] = acc[i][j];
}

// =====================================================================
// K5: RoPE
// =====================================================================
__global__ void k_rope()
{
    int m = blockIdx.x;
    int i = threadIdx.x;
    int s = m & (SS - 1);
    float invf = powf(10000.f, -((float)(2 * i) / (float)DD));
    float ang = (float)s * invf;
    float sn, cs;
    sincosf(ang, &sn, &cs);
    size_t base = (size_t)m * DD + 2 * i;
    float q0 = d_Q[base], q1 = d_Q[base + 1];
    d_Q[base]     = q0 * cs - q1 * sn;
    d_Q[base + 1] = q1 * cs + q0 * sn;
    float k0 = d_Kc[base], k1 = d_Kc[base + 1];
    d_Kc[base]     = k0 * cs - k1 * sn;
    d_Kc[base + 1] = k1 * cs + k0 * sn;
}

// =====================================================================
// K6: scores
// =====================================================================
__global__ void k_scores()
{
    const int z = blockIdx.z;
    const int m0 = blockIdx.y * 64;
    const int n0 = blockIdx.x * 64;
    const int t = threadIdx.x;
    float* C = d_probs + (size_t)z * SS * SS;

    if (n0 >= m0 + 64) {
        for (int e = t; e < 64 * 64; e += 256) {
            int i = e >> 6, j = e & 63;
            C[(size_t)(m0 + i) * SS + n0 + j] = -1e30f;
        }
        return;
    }

    const float* A = d_Q + (size_t)z * SS * DD;
    const float* Bm = d_Kc + (size_t)z * SS * DD;
    __shared__ float As[16][64];
    __shared__ float Bs[16][64];
    const int lrow = t >> 2, lk4 = (t & 3) * 4;
    const int ty = t >> 4, tx = t & 15;
    float acc[4][4];
#pragma unroll
    for (int i = 0; i < 4; i++)
#pragma unroll
        for (int j = 0; j < 4; j++) acc[i][j] = 0.f;

    for (int k0 = 0; k0 < DD; k0 += 16) {
        float4 a = *(const float4*)&A[(size_t)(m0 + lrow) * DD + k0 + lk4];
        float4 bv = *(const float4*)&Bm[(size_t)(n0 + lrow) * DD + k0 + lk4];
        As[lk4 + 0][lrow] = a.x; As[lk4 + 1][lrow] = a.y;
        As[lk4 + 2][lrow] = a.z; As[lk4 + 3][lrow] = a.w;
        Bs[lk4 + 0][lrow] = bv.x; Bs[lk4 + 1][lrow] = bv.y;
        Bs[lk4 + 2][lrow] = bv.z; Bs[lk4 + 3][lrow] = bv.w;
        __syncthreads();
#pragma unroll
        for (int kk = 0; kk < 16; kk++) {
            float4 av = *(float4*)&As[kk][ty * 4];
            float4 bv2 = *(float4*)&Bs[kk][tx * 4];
            float a2[4] = {av.x, av.y, av.z, av.w};
            float b2[4] = {bv2.x, bv2.y, bv2.z, bv2.w};
#pragma unroll
            for (int i = 0; i < 4; i++)
#pragma unroll
                for (int j = 0; j < 4; j++) acc[i][j] += a2[i] * b2[j];
        }
        __syncthreads();
    }
    const float scale = 0.04419417382415922f;
#pragma unroll
    for (int i = 0; i < 4; i++) {
        int gi = m0 + ty * 4 + i;
#pragma unroll
        for (int j = 0; j < 4; j++) {
            int gj = n0 + tx * 4 + j;
            float v = acc[i][j] * scale;
            if (gj > gi) v = -1e30f;
            C[(size_t)gi * SS + gj] = v;
        }
    }
}

// =====================================================================
// K7: row softmax over 1024
// =====================================================================
__global__ void k_softmax_rows()
{
    int m = blockIdx.x;
    float* row = d_probs + (size_t)m * SS;
    const int t = threadIdx.x;
    __shared__ float red[256];

    float4 lv = *(float4*)&row[t * 4];
    float mx = fmaxf(fmaxf(lv.x, lv.y), fmaxf(lv.z, lv.w));
    red[t] = mx;
    __syncthreads();
    for (int off = 128; off > 0; off >>= 1) {
        if (t < off) red[t] = fmaxf(red[t], red[t + off]);
        __syncthreads();
    }
    mx = red[0];
    __syncthreads();

    float4 e;
    e.x = expf(lv.x - mx); e.y = expf(lv.y - mx);
    e.z = expf(lv.z - mx); e.w = expf(lv.w - mx);
    red[t] = e.x + e.y + e.z + e.w;
    __syncthreads();
    for (int off = 128; off > 0; off >>= 1) {
        if (t < off) red[t] += red[t + off];
        __syncthreads();
    }
    float inv = 1.f / red[0];
    e.x *= inv; e.y *= inv; e.z *= inv; e.w *= inv;
    *(float4*)&row[t * 4] = e;
}

// =====================================================================
// K8: context = probs @ gru
// =====================================================================
__global__ void k_ctx()
{
    const int z = blockIdx.z;
    const int m0 = blockIdx.y * 64;
    const int n0 = blockIdx.x * 64;
    const float* A = d_probs + (size_t)z * SS * SS;
    const float* Bm = d_gru + (size_t)z * SS * DD;
    float* C = d_ctx + (size_t)z * SS * DD;

    __shared__ float As[16][64];
    __shared__ float Bs[16][64];
    const int t = threadIdx.x;
    const int lrow = t >> 2, lk4 = (t & 3) * 4;
    const int bk = t >> 4, bn4 = (t & 15) * 4;
    const int ty = t >> 4, tx = t & 15;
    float acc[4][4];
#pragma unroll
    for (int i = 0; i < 4; i++)
#pragma unroll
        for (int j = 0; j < 4; j++) acc[i][j] = 0.f;

    for (int k0 = 0; k0 < SS; k0 += 16) {
        float4 a = *(const float4*)&A[(size_t)(m0 + lrow) * SS + k0 + lk4];
        As[lk4 + 0][lrow] = a.x; As[lk4 + 1][lrow] = a.y;
        As[lk4 + 2][lrow] = a.z; As[lk4 + 3][lrow] = a.w;
        float4 bv = *(const float4*)&Bm[(size_t)(k0 + bk) * DD + n0 + bn4];
        *(float4*)&Bs[bk][bn4] = bv;
        __syncthreads();
#pragma unroll
        for (int kk = 0; kk < 16; kk++) {
            float4 av = *(float4*)&As[kk][ty * 4];
            float4 bv2 = *(float4*)&Bs[kk][tx * 4];
            float a2[4] = {av.x, av.y, av.z, av.w};
            float b2[4] = {bv2.x, bv2.y, bv2.z, bv2.w};
#pragma unroll
            for (int i = 0; i < 4; i++)
#pragma unroll
                for (int j = 0; j < 4; j++) acc[i][j] += a2[i] * b2[j];
        }
        __syncthreads();
    }
#pragma unroll
    for (int i = 0; i < 4; i++)
#pragma unroll
        for (int j = 0; j < 4; j++)
            C[(size_t)(m0 + ty * 4 + i) * DD + n0 + tx * 4 + j] = acc[i][j];
}

// =====================================================================
// K9: combined (e4m3 x16) + gate
// =====================================================================
__global__ void k_comb_gate(const float* __restrict__ gate_W,
                            const float* __restrict__ gate_b)
{
    int m = blockIdx.x;
    int t = threadIdx.x;
    __shared__ float red[256];
    int idx = t * 2;
    float g0 = d_gru[(size_t)m * DD + idx];
    float g1 = d_gru[(size_t)m * DD + idx + 1];
    float c0 = d_ctx[(size_t)m * DD + idx];
    float c1 = d_ctx[(size_t)m * DD + idx + 1];
    uint16_t pg = cvt_e4m3x2(g1 * 16.f, g0 * 16.f);
    uint16_t pc = cvt_e4m3x2(c1 * 16.f, c0 * 16.f);
    *(uint16_t*)&d_comb_f8[(size_t)m * 2 * DD + idx] = pg;
    *(uint16_t*)&d_comb_f8[(size_t)m * 2 * DD + DD + idx] = pc;
    float acc = g0 * gate_W[idx] + g1 * gate_W[idx + 1]
              + c0 * gate_W[DD + idx] + c1 * gate_W[DD + idx + 1];
    red[t] = acc;
    __syncthreads();
    for (int off = 128; off > 0; off >>= 1) {
        if (t < off) red[t] += red[t + off];
        __syncthreads();
    }
    if (t == 0) d_gate[m] = 1.f / (1.f + expf(-(red[0] + gate_b[0])));
}

// =====================================================================
// K10: gen logits GEMM, mma.sync e4m3 m16n8k32 + ldmatrix + 3-stage
// cp.async. logits = (comb_f8 @ genW_f8^T)/1024 + bias
// CTA 128x128, KC=128 elems (=128B rows, SW128), 8 chunks. m-fast grid.
// =====================================================================
__device__ __forceinline__ void mma_f8(float& c0, float& c1, float& c2, float& c3,
                                       uint32_t a0, uint32_t a1, uint32_t a2, uint32_t a3,
                                       uint32_t b0, uint32_t b1)
{
    asm volatile(
        "mma.sync.aligned.m16n8k32.row.col.f32.e4m3.e4m3.f32 "
        "{%0,%1,%2,%3}, {%4,%5,%6,%7}, {%8,%9}, {%0,%1,%2,%3};\n"
        : "+f"(c0), "+f"(c1), "+f"(c2), "+f"(c3)
        : "r"(a0), "r"(a1), "r"(a2), "r"(a3), "r"(b0), "r"(b1));
}
__device__ __forceinline__ void cp16s(uint32_t saddr, const void* g)
{
    asm volatile("cp.async.cg.shared.global [%0], [%1], 16;\n" :: "r"(saddr), "l"(g));
}
__device__ __forceinline__ void ldsm4(uint32_t& r0, uint32_t& r1, uint32_t& r2,
                                      uint32_t& r3, uint32_t addr)
{
    asm volatile("ldmatrix.sync.aligned.m8n8.x4.shared.b16 {%0,%1,%2,%3}, [%4];"
                 : "=r"(r0), "=r"(r1), "=r"(r2), "=r"(r3) : "r"(addr));
}
#define SWZ(o) ((o) ^ (((o) >> 3) & 0x70))
#define FSTG 3
#define FSTAGE_BYTES 32768           // A 16KB + B 16KB
#define FSMEM (FSTG * FSTAGE_BYTES)  // 96KB

__global__ void __launch_bounds__(256, 2) k_gen_f8(const float* __restrict__ bias)
{
    extern __shared__ __align__(1024) char gsm[];
    uint32_t sbase;
    asm("{ .reg .u64 t; cvta.to.shared.u64 t, %1; cvt.u32.u64 %0, t; }"
        : "=r"(sbase) : "l"(gsm));

    const int m0 = blockIdx.x * 128;
    const int n0 = blockIdx.y * 128;
    const int t = threadIdx.x;
    const int w = t >> 5, lane = t & 31;
    const int wm = (w >> 2) * 64;
    const int wn = (w & 3) * 32;
    const int g = lane >> 2, q = lane & 3;

    // ldmatrix per-lane row/col selectors (16B granularity)
    const int a_row = ((lane >> 3) & 1) * 8 + (lane & 7);
    const int a_colb = ((lane >> 4) & 1) * 16;
    const int b_row = (lane >> 4) * 8 + (lane & 7);
    const int b_colb = ((lane >> 3) & 1) * 16;

    const char* Ag = (const char*)&d_comb_f8[(size_t)m0 * 1024];
    const char* Bg = (const char*)&d_genW_f8[(size_t)n0 * 1024];

    float acc[4][4][4];
#pragma unroll
    for (int i = 0; i < 4; i++)
#pragma unroll
        for (int j = 0; j < 4; j++)
#pragma unroll
            for (int r = 0; r < 4; r++) acc[i][j][r] = 0.f;

    auto stage = [&](int st, int c) {
        uint32_t aB = sbase + st * FSTAGE_BYTES;
        uint32_t bB = aB + 16384;
        int kb = c * 128;                       // bytes into K
#pragma unroll
        for (int it = 0; it < 4; it++) {
            int idx = it * 256 + t;
            int row = idx >> 3;
            int p = (idx & 7) * 16;
            cp16s(aB + SWZ(row * 128 + p), Ag + (size_t)row * 1024 + kb + p);
            cp16s(bB + SWZ(row * 128 + p), Bg + (size_t)row * 1024 + kb + p);
        }
        asm volatile("cp.async.commit_group;" ::);
    };

    stage(0, 0);
    stage(1, 1);

#pragma unroll 1
    for (int c = 0; c < 8; c++) {
        if (c < 7) asm volatile("cp.async.wait_group 1;" ::);
        else       asm volatile("cp.async.wait_group 0;" ::);
        __syncthreads();

        const int st = c % FSTG;
        const uint32_t aB = sbase + st * FSTAGE_BYTES;
        const uint32_t bB = aB + 16384;

#pragma unroll
        for (int kkb = 0; kkb < 128; kkb += 32) {   // k=32 per mma
            uint32_t af[4][4];
#pragma unroll
            for (int i = 0; i < 4; i++) {
                int row = wm + i * 16 + a_row;
                ldsm4(af[i][0], af[i][1], af[i][2], af[i][3],
                      aB + SWZ(row * 128 + kkb + a_colb));
            }
            uint32_t bf[4][2];
#pragma unroll
            for (int j2 = 0; j2 < 2; j2++) {
                int row = wn + j2 * 16 + b_row;
                ldsm4(bf[j2 * 2][0], bf[j2 * 2][1], bf[j2 * 2 + 1][0], bf[j2 * 2 + 1][1],
                      bB + SWZ(row * 128 + kkb + b_colb));
            }
#pragma unroll
            for (int i = 0; i < 4; i++)
#pragma unroll
                for (int j = 0; j < 4; j++)
                    mma_f8(acc[i][j][0], acc[i][j][1], acc[i][j][2], acc[i][j][3],
                           af[i][0], af[i][1], af[i][2], af[i][3],
                           bf[j][0], bf[j][1]);
        }
        __syncthreads();
        if (c + 2 < 8) stage((c + 2) % FSTG, c + 2);
    }

    // epilogue: descale (1/(16*64)) + bias
    const float ds = 0.0009765625f;
#pragma unroll
    for (int j = 0; j < 4; j++) {
        int n = n0 + wn + j * 8 + q * 2;
        float2 bv = *(const float2*)&bias[n];
#pragma unroll
        for (int i = 0; i < 4; i++) {
            size_t r0 = (size_t)(m0 + wm + i * 16 + g);
            size_t r1 = r0 + 8;
            float2 o0 = {acc[i][j][0] * ds + bv.x, acc[i][j][1] * ds + bv.y};
            float2 o1 = {acc[i][j][2] * ds + bv.x, acc[i][j][3] * ds + bv.y};
            *(float2*)&d_logits[r0 * VV + n] = o0;
            *(float2*)&d_logits[r1 * VV + n] = o1;
        }
    }
}

// =====================================================================
// K11: fused row softmax over V + gate blend -> out
// =====================================================================
__global__ void k_softmaxV(float* __restrict__ out)
{
    int m = blockIdx.x;
    const float* row = d_logits + (size_t)m * VV;
    const int t = threadIdx.x;
    float mx = -1e30f, sm = 0.f;
    for (int v4 = t; v4 < VV / 4; v4 += 256) {
        float4 l = *(const float4*)&row[v4 * 4];
        float vals[4] = {l.x, l.y, l.z, l.w};
#pragma unroll
        for (int u = 0; u < 4; u++) {
            float l1 = vals[u];
            if (l1 > mx) { sm = sm * __expf(mx - l1) + 1.f; mx = l1; }
            else sm += __expf(l1 - mx);
        }
    }
    __shared__ float smx[256], ssm[256];
    smx[t] = mx; ssm[t] = sm;
    for (int off = 128; off > 0; off >>= 1) {
        __syncthreads();
        if (t < off) {
            float m2 = smx[t + off], s2 = ssm[t + off];
            if (m2 > mx) { sm = sm * __expf(mx - m2) + s2; mx = m2; }
            else sm += s2 * __expf(m2 - mx);
            smx[t] = mx; ssm[t] = sm;
        }
    }
    __syncthreads();
    mx = smx[0];
    float g = d_gate[m];
    float is = g / ssm[0];
    float* orow = out + (size_t)m * VV;
    for (int v4 = t; v4 < VV / 4; v4 += 256) {
        float4 l = *(const float4*)&row[v4 * 4];
        float4 o;
        o.x = __expf(l.x - mx) * is;
        o.y = __expf(l.y - mx) * is;
        o.z = __expf(l.z - mx) * is;
        o.w = __expf(l.w - mx) * is;
        *(float4*)&orow[v4 * 4] = o;
    }
}

// =====================================================================
// K13: scatter copy-probs
// =====================================================================
__global__ void k_scatter(const int* __restrict__ x, float* __restrict__ out)
{
    int m = blockIdx.x;
    int b = m >> 10;
    int i = m & (SS - 1);
    float om = 1.f - d_gate[m];
    const float* pr = d_probs + (size_t)m * SS;
    float* orow = out + (size_t)m * VV;
    for (int j = threadIdx.x; j <= i; j += 256) {
        atomicAdd(&orow[x[b * SS + j]], om * pr[j]);
    }
}

// =====================================================================
// launch
// =====================================================================
extern "C" void kernel_launch(void* const* d_in, const int* in_sizes, int n_in,
                              void* d_out, int out_size)
{
    const int*   x        = (const int*)d_in[0];
    const float* tok_emb  = (const float*)d_in[1];
    const float* pos_emb  = (const float*)d_in[2];
    const float* W_ih     = (const float*)d_in[3];
    const float* W_hh     = (const float*)d_in[4];
    const float* b_ih     = (const float*)d_in[5];
    const float* b_hh     = (const float*)d_in[6];
    const float* W_q      = (const float*)d_in[7];
    const float* W_k      = (const float*)d_in[8];
    const float* gen_W    = (const float*)d_in[9];
    const float* gen_b    = (const float*)d_in[10];
    const float* gate_W   = (const float*)d_in[11];
    const float* gate_b   = (const float*)d_in[12];
    float* out = (float*)d_out;

    cudaFuncSetAttribute(k_gen_f8, cudaFuncAttributeMaxDynamicSharedMemorySize,
                         FSMEM);

    k_xproj<<<dim3(G3 / 64, MM / 64), 256>>>(x, tok_emb, pos_emb, W_ih, b_ih);
    k_init<<<1, 256>>>();
    k_convW8<<<(VV * 2 * DD) / (8 * 256), 256>>>(gen_W);
    k_gru<<<GRU_CTAS, 256>>>(W_hh, b_hh);
    k_qk<0><<<dim3(DD / 64, MM / 64), 256>>>(W_q);
    k_qk<1><<<dim3(DD / 64, MM / 64), 256>>>(W_k);
    k_rope<<<MM, 256>>>();
    k_scores<<<dim3(SS / 64, SS / 64, BB), 256>>>();
    k_softmax_rows<<<MM, 256>>>();
    k_ctx<<<dim3(DD / 64, SS / 64, BB), 256>>>();
    k_comb_gate<<<MM, 256>>>(gate_W, gate_b);
    k_gen_f8<<<dim3(MM / 128, VV / 128), 256, FSMEM>>>(gen_b);
    k_softmaxV<<<MM, 256>>>(out);
    k_scatter<<<MM, 256>>>(x, out);
}